// round 1
// baseline (speedup 1.0000x reference)
#include <cuda_runtime.h>
#include <math.h>

// Problem constants
#define BB 2
#define SS 2048
#define HH 1024
#define NH 16
#define DD 64

// Scratch: split-head Q/K/V [B, NH, S, D] and pre-Wo attention output [B*S, H]
__device__ float g_Q[(size_t)BB * NH * SS * DD];
__device__ float g_K[(size_t)BB * NH * SS * DD];
__device__ float g_V[(size_t)BB * NH * SS * DD];
__device__ float g_A[(size_t)BB * SS * HH];

// ---------------------------------------------------------------------------
// Fused conv1d('SAME', KS taps) + bias + optional scale as a tiled SGEMM.
// Y[m,n] = (sum_{tap} sum_c X[b, t+tap-CENTER, c] * W[tap, c, n] + bias[n]) * scale
// where m = b*SS + t. Rows outside [0,SS) are zero-padded.
// BM=128, BN=128, BK=16, 256 threads, 8x8 outputs/thread.
// HEADS_OUT: write to [B, NH, S, D] split-head layout; else flat [M, H].
// ---------------------------------------------------------------------------
template <int TAPS, bool HEADS_OUT>
__global__ __launch_bounds__(256) void gemm_conv_kernel(
    const float* __restrict__ X, const float* __restrict__ W,
    const float* __restrict__ bias, float* __restrict__ Y, float scale)
{
    __shared__ float As[16][132];   // [k][m] transposed A tile
    __shared__ float Bs[16][132];   // [k][n]

    const int n0 = blockIdx.x * 128;
    const int m0 = blockIdx.y * 128;
    const int tid = threadIdx.x;
    const int tr = tid >> 4;        // 0..15 : row group (8 rows)
    const int tc = tid & 15;        // 0..15 : col group (8 cols)

    float acc[8][8];
#pragma unroll
    for (int i = 0; i < 8; ++i)
#pragma unroll
        for (int j = 0; j < 8; ++j) acc[i][j] = 0.f;

    const int CENTER = (TAPS - 1) / 2;

    for (int tap = 0; tap < TAPS; ++tap) {
        const float* Wt = W + (size_t)tap * HH * HH;
        for (int c0 = 0; c0 < HH; c0 += 16) {
            // Load A tile: 128 rows x 16 cols (2 float4 per thread), store transposed
#pragma unroll
            for (int p = 0; p < 2; ++p) {
                int f = tid + p * 256;
                int row = f >> 2;
                int c4 = (f & 3) << 2;
                int m = m0 + row;
                int bidx = m >> 11;          // / SS
                int t = m & (SS - 1);
                int srow = t + tap - CENTER;
                float4 v = make_float4(0.f, 0.f, 0.f, 0.f);
                if (srow >= 0 && srow < SS)
                    v = *(const float4*)(X + ((size_t)bidx * SS + srow) * HH + c0 + c4);
                As[c4 + 0][row] = v.x;
                As[c4 + 1][row] = v.y;
                As[c4 + 2][row] = v.z;
                As[c4 + 3][row] = v.w;
            }
            // Load B tile: 16 rows x 128 cols (2 float4 per thread)
#pragma unroll
            for (int p = 0; p < 2; ++p) {
                int f = tid + p * 256;
                int kk = f >> 5;
                int c4 = (f & 31) << 2;
                *(float4*)&Bs[kk][c4] =
                    *(const float4*)(Wt + (size_t)(c0 + kk) * HH + n0 + c4);
            }
            __syncthreads();

#pragma unroll
            for (int kk = 0; kk < 16; ++kk) {
                float a[8], b[8];
                *(float4*)&a[0] = *(const float4*)&As[kk][tr * 8];
                *(float4*)&a[4] = *(const float4*)&As[kk][tr * 8 + 4];
                *(float4*)&b[0] = *(const float4*)&Bs[kk][tc * 8];
                *(float4*)&b[4] = *(const float4*)&Bs[kk][tc * 8 + 4];
#pragma unroll
                for (int i = 0; i < 8; ++i)
#pragma unroll
                    for (int j = 0; j < 8; ++j)
                        acc[i][j] = fmaf(a[i], b[j], acc[i][j]);
            }
            __syncthreads();
        }
    }

    // Epilogue: bias, scale, layout
#pragma unroll
    for (int i = 0; i < 8; ++i) {
        int m = m0 + tr * 8 + i;
        int bidx = m >> 11;
        int t = m & (SS - 1);
#pragma unroll
        for (int j = 0; j < 8; j += 4) {
            int n = n0 + tc * 8 + j;
            float4 o;
            o.x = (acc[i][j + 0] + bias[n + 0]) * scale;
            o.y = (acc[i][j + 1] + bias[n + 1]) * scale;
            o.z = (acc[i][j + 2] + bias[n + 2]) * scale;
            o.w = (acc[i][j + 3] + bias[n + 3]) * scale;
            if (HEADS_OUT) {
                int h = n >> 6;
                int d = n & 63;
                *(float4*)(Y + (((size_t)bidx * NH + h) * SS + t) * DD + d) = o;
            } else {
                *(float4*)(Y + (size_t)m * HH + n) = o;
            }
        }
    }
}

// ---------------------------------------------------------------------------
// Flash-style attention: one block per (b, h, 64-query tile).
// 256 threads = 16x16; each thread owns a 4x4 fragment of the 64x64 tiles.
// smem = Qs (Q^T) + KP (K^T, reused as P) + Vs = exactly 48 KB.
// ---------------------------------------------------------------------------
__global__ __launch_bounds__(256) void attn_kernel(const float* __restrict__ mask,
                                                   float* __restrict__ Aout)
{
    __shared__ float Qs[64][64];  // [d][qrow]
    __shared__ float KP[64][64];  // phase 1: K^T [d][kcol]; phase 2: P [qrow][kcol]
    __shared__ float Vs[64][64];  // [kcol][d]

    const int q0 = blockIdx.x * 64;
    const int h = blockIdx.y;
    const int b = blockIdx.z;
    const int tid = threadIdx.x;
    const int ty = tid >> 4;  // query-row group
    const int tx = tid & 15;  // key/d col group
    const size_t base = ((size_t)b * NH + h) * SS * DD;

    // Load Q tile transposed
#pragma unroll
    for (int p = 0; p < 4; ++p) {
        int f = tid + p * 256;
        int r = f >> 4;
        int d4 = (f & 15) << 2;
        float4 v = *(const float4*)(g_Q + base + (size_t)(q0 + r) * DD + d4);
        Qs[d4 + 0][r] = v.x;
        Qs[d4 + 1][r] = v.y;
        Qs[d4 + 2][r] = v.z;
        Qs[d4 + 3][r] = v.w;
    }

    float o[4][4];
    float mrow[4], lrow[4];
#pragma unroll
    for (int i = 0; i < 4; ++i) {
        mrow[i] = -1e30f;
        lrow[i] = 0.f;
#pragma unroll
        for (int j = 0; j < 4; ++j) o[i][j] = 0.f;
    }

    for (int k0 = 0; k0 < SS; k0 += 64) {
        __syncthreads();  // previous tile fully consumed (also covers Q load)
        // Load K tile transposed + V tile natural
#pragma unroll
        for (int p = 0; p < 4; ++p) {
            int f = tid + p * 256;
            int r = f >> 4;
            int d4 = (f & 15) << 2;
            float4 kv = *(const float4*)(g_K + base + (size_t)(k0 + r) * DD + d4);
            KP[d4 + 0][r] = kv.x;
            KP[d4 + 1][r] = kv.y;
            KP[d4 + 2][r] = kv.z;
            KP[d4 + 3][r] = kv.w;
            *(float4*)&Vs[r][d4] =
                *(const float4*)(g_V + base + (size_t)(k0 + r) * DD + d4);
        }
        __syncthreads();

        // S = Q K^T (4x4 fragment per thread)
        float s[4][4];
#pragma unroll
        for (int i = 0; i < 4; ++i)
#pragma unroll
            for (int j = 0; j < 4; ++j) s[i][j] = 0.f;
#pragma unroll 16
        for (int d = 0; d < 64; ++d) {
            float a[4], bb[4];
            *(float4*)&a[0]  = *(const float4*)&Qs[d][ty * 4];
            *(float4*)&bb[0] = *(const float4*)&KP[d][tx * 4];
#pragma unroll
            for (int i = 0; i < 4; ++i)
#pragma unroll
                for (int j = 0; j < 4; ++j)
                    s[i][j] = fmaf(a[i], bb[j], s[i][j]);
        }

        // Additive mask: logits += mask[b, k] * (-1e9)
#pragma unroll
        for (int j = 0; j < 4; ++j) {
            float mk = mask[(size_t)b * SS + k0 + tx * 4 + j] * (-1e9f);
#pragma unroll
            for (int i = 0; i < 4; ++i) s[i][j] += mk;
        }

        // Online softmax (row reductions across the 16 tx lanes of each row group)
        float pr[4][4];
#pragma unroll
        for (int i = 0; i < 4; ++i) {
            float tm = fmaxf(fmaxf(s[i][0], s[i][1]), fmaxf(s[i][2], s[i][3]));
#pragma unroll
            for (int off = 8; off; off >>= 1)
                tm = fmaxf(tm, __shfl_xor_sync(0xffffffffu, tm, off));
            float nm = fmaxf(mrow[i], tm);
            float ts = 0.f;
#pragma unroll
            for (int j = 0; j < 4; ++j) {
                pr[i][j] = __expf(s[i][j] - nm);
                ts += pr[i][j];
            }
#pragma unroll
            for (int off = 8; off; off >>= 1)
                ts += __shfl_xor_sync(0xffffffffu, ts, off);
            float corr = __expf(mrow[i] - nm);
            lrow[i] = lrow[i] * corr + ts;
            mrow[i] = nm;
#pragma unroll
            for (int j = 0; j < 4; ++j) o[i][j] *= corr;
        }

        __syncthreads();  // done reading KP as K
        // Stage P into KP as [qrow][kcol]
#pragma unroll
        for (int i = 0; i < 4; ++i)
            *(float4*)&KP[ty * 4 + i][tx * 4] =
                make_float4(pr[i][0], pr[i][1], pr[i][2], pr[i][3]);
        __syncthreads();

        // O += P V
#pragma unroll 16
        for (int kk = 0; kk < 64; ++kk) {
            float4 bv = *(const float4*)&Vs[kk][tx * 4];
            float a0 = KP[ty * 4 + 0][kk];
            float a1 = KP[ty * 4 + 1][kk];
            float a2 = KP[ty * 4 + 2][kk];
            float a3 = KP[ty * 4 + 3][kk];
            o[0][0] = fmaf(a0, bv.x, o[0][0]); o[0][1] = fmaf(a0, bv.y, o[0][1]);
            o[0][2] = fmaf(a0, bv.z, o[0][2]); o[0][3] = fmaf(a0, bv.w, o[0][3]);
            o[1][0] = fmaf(a1, bv.x, o[1][0]); o[1][1] = fmaf(a1, bv.y, o[1][1]);
            o[1][2] = fmaf(a1, bv.z, o[1][2]); o[1][3] = fmaf(a1, bv.w, o[1][3]);
            o[2][0] = fmaf(a2, bv.x, o[2][0]); o[2][1] = fmaf(a2, bv.y, o[2][1]);
            o[2][2] = fmaf(a2, bv.z, o[2][2]); o[2][3] = fmaf(a2, bv.w, o[2][3]);
            o[3][0] = fmaf(a3, bv.x, o[3][0]); o[3][1] = fmaf(a3, bv.y, o[3][1]);
            o[3][2] = fmaf(a3, bv.z, o[3][2]); o[3][3] = fmaf(a3, bv.w, o[3][3]);
        }
    }

    // Normalize and write merged-head layout [B, S, H] (H index = h*64 + d)
#pragma unroll
    for (int i = 0; i < 4; ++i) {
        int q = q0 + ty * 4 + i;
        float inv = 1.f / lrow[i];
        float4 v = make_float4(o[i][0] * inv, o[i][1] * inv,
                               o[i][2] * inv, o[i][3] * inv);
        *(float4*)(Aout + ((size_t)b * SS + q) * HH + h * DD + tx * 4) = v;
    }
}

// ---------------------------------------------------------------------------
extern "C" void kernel_launch(void* const* d_in, const int* in_sizes, int n_in,
                              void* d_out, int out_size)
{
    const float* qin  = (const float*)d_in[0];
    const float* src  = (const float*)d_in[1];
    const float* mask = (const float*)d_in[2];
    const float* Wq   = (const float*)d_in[3];
    const float* bq   = (const float*)d_in[4];
    const float* Wk   = (const float*)d_in[5];
    const float* bk   = (const float*)d_in[6];
    const float* Wv   = (const float*)d_in[7];
    const float* bv   = (const float*)d_in[8];
    const float* Wo   = (const float*)d_in[9];
    const float* bo   = (const float*)d_in[10];
    float* out = (float*)d_out;

    float *gQ, *gK, *gV, *gA;
    cudaGetSymbolAddress((void**)&gQ, g_Q);
    cudaGetSymbolAddress((void**)&gK, g_K);
    cudaGetSymbolAddress((void**)&gV, g_V);
    cudaGetSymbolAddress((void**)&gA, g_A);

    dim3 gridProj(HH / 128, (BB * SS) / 128);  // (8, 32)
    gemm_conv_kernel<3, true><<<gridProj, 256>>>(qin, Wq, bq, gQ, 0.125f);  // D^-0.5
    gemm_conv_kernel<3, true><<<gridProj, 256>>>(src, Wk, bk, gK, 1.0f);
    gemm_conv_kernel<3, true><<<gridProj, 256>>>(src, Wv, bv, gV, 1.0f);

    dim3 gridAttn(SS / 64, NH, BB);  // (32, 16, 2)
    attn_kernel<<<gridAttn, 256>>>(mask, gA);

    gemm_conv_kernel<1, false><<<gridProj, 256>>>(gA, Wo, bo, out, 1.0f);
}

// round 2
// speedup vs baseline: 1.6252x; 1.6252x over previous
#include <cuda_runtime.h>
#include <math.h>
#include <stdint.h>

// Problem constants
#define BB 2
#define SS 2048
#define HH 1024
#define NH 16
#define DD 64

// Scratch: split-head Q/K/V [B, NH, S, D] and pre-Wo attention output [B*S, H]
__device__ float g_Q[(size_t)BB * NH * SS * DD];
__device__ float g_K[(size_t)BB * NH * SS * DD];
__device__ float g_V[(size_t)BB * NH * SS * DD];
__device__ float g_A[(size_t)BB * SS * HH];

// ---------------------------------------------------------------------------
// tf32 helpers
// ---------------------------------------------------------------------------
__device__ __forceinline__ uint32_t f2tf32(float x) {
    uint32_t r;
    asm("cvt.rna.tf32.f32 %0, %1;" : "=r"(r) : "f"(x));
    return r;
}

__device__ __forceinline__ void mma_tf32(float* d, const uint32_t* a, const uint32_t* b) {
    asm volatile(
        "mma.sync.aligned.m16n8k8.row.col.f32.tf32.tf32.f32 "
        "{%0,%1,%2,%3}, {%4,%5,%6,%7}, {%8,%9}, {%0,%1,%2,%3};"
        : "+f"(d[0]), "+f"(d[1]), "+f"(d[2]), "+f"(d[3])
        : "r"(a[0]), "r"(a[1]), "r"(a[2]), "r"(a[3]), "r"(b[0]), "r"(b[1]));
}

// ---------------------------------------------------------------------------
// Fused conv1d('SAME', TAPS) + bias + scale as a tf32 tensor-core GEMM.
// Y[m,n] = (sum_tap sum_c X[b, t+tap-CENTER, c] * W[tap,c,n] + bias[n]) * scale
// BM=128, BN=128, BK=16. 256 threads = 8 warps (2 m x 4 n), warp tile 64x32.
// Each warp: 4 m16-frags x 4 n8-frags, mma.sync m16n8k8 tf32.
// smem stride 136 => fragment LDS bank = 8*(k%4) + (m%8): conflict-free.
// ---------------------------------------------------------------------------
template <int TAPS, bool HEADS_OUT>
__global__ __launch_bounds__(256) void gemm_conv_tc(
    const float* __restrict__ X, const float* __restrict__ W,
    const float* __restrict__ bias, float* __restrict__ Y, float scale)
{
    __shared__ uint32_t As[16][136];   // [k][m], tf32 bits
    __shared__ uint32_t Bs[16][136];   // [k][n], tf32 bits

    const int n0 = blockIdx.x * 128;
    const int m0 = blockIdx.y * 128;
    const int tid = threadIdx.x;
    const int wid = tid >> 5;
    const int lane = tid & 31;
    const int g = lane >> 2;     // 0..7
    const int tg = lane & 3;     // 0..3
    const int warp_m = wid >> 2;         // 0..1  -> m offset 64*warp_m
    const int warp_n = wid & 3;          // 0..3  -> n offset 32*warp_n

    float acc[4][4][4];                  // [mt][nt][reg]
#pragma unroll
    for (int i = 0; i < 4; ++i)
#pragma unroll
        for (int j = 0; j < 4; ++j)
#pragma unroll
            for (int r = 0; r < 4; ++r) acc[i][j][r] = 0.f;

    const int CENTER = (TAPS - 1) / 2;

    for (int tap = 0; tap < TAPS; ++tap) {
        const float* Wt = W + (size_t)tap * HH * HH;
        for (int c0 = 0; c0 < HH; c0 += 16) {
            // --- stage A: 128 rows x 16 k (transposed into [k][m]) ---
#pragma unroll
            for (int p = 0; p < 2; ++p) {
                int f = tid + p * 256;
                int row = f >> 2;
                int c4 = (f & 3) << 2;
                int m = m0 + row;
                int bidx = m >> 11;
                int t = m & (SS - 1);
                int srow = t + tap - CENTER;
                float4 v = make_float4(0.f, 0.f, 0.f, 0.f);
                if (srow >= 0 && srow < SS)
                    v = *(const float4*)(X + ((size_t)bidx * SS + srow) * HH + c0 + c4);
                As[c4 + 0][row] = f2tf32(v.x);
                As[c4 + 1][row] = f2tf32(v.y);
                As[c4 + 2][row] = f2tf32(v.z);
                As[c4 + 3][row] = f2tf32(v.w);
            }
            // --- stage B: 16 k x 128 n (natural [k][n], vector STS) ---
#pragma unroll
            for (int p = 0; p < 2; ++p) {
                int f = tid + p * 256;
                int kk = f >> 5;
                int c4 = (f & 31) << 2;
                float4 v = *(const float4*)(Wt + (size_t)(c0 + kk) * HH + n0 + c4);
                uint4 u;
                u.x = f2tf32(v.x); u.y = f2tf32(v.y);
                u.z = f2tf32(v.z); u.w = f2tf32(v.w);
                *(uint4*)&Bs[kk][c4] = u;
            }
            __syncthreads();

#pragma unroll
            for (int ks = 0; ks < 2; ++ks) {
                const int kb = ks * 8;
                uint32_t a[4][4];
                uint32_t b[4][2];
#pragma unroll
                for (int mt = 0; mt < 4; ++mt) {
                    int mr = warp_m * 64 + mt * 16 + g;
                    a[mt][0] = As[kb + tg][mr];
                    a[mt][1] = As[kb + tg][mr + 8];
                    a[mt][2] = As[kb + tg + 4][mr];
                    a[mt][3] = As[kb + tg + 4][mr + 8];
                }
#pragma unroll
                for (int nt = 0; nt < 4; ++nt) {
                    int nc = warp_n * 32 + nt * 8 + g;
                    b[nt][0] = Bs[kb + tg][nc];
                    b[nt][1] = Bs[kb + tg + 4][nc];
                }
#pragma unroll
                for (int mt = 0; mt < 4; ++mt)
#pragma unroll
                    for (int nt = 0; nt < 4; ++nt)
                        mma_tf32(acc[mt][nt], a[mt], b[nt]);
            }
            __syncthreads();
        }
    }

    // --- epilogue: bias, scale, layout ---
#pragma unroll
    for (int mt = 0; mt < 4; ++mt) {
#pragma unroll
        for (int half = 0; half < 2; ++half) {          // row g / row g+8
            int m = m0 + warp_m * 64 + mt * 16 + g + half * 8;
            int bidx = m >> 11;
            int t = m & (SS - 1);
#pragma unroll
            for (int nt = 0; nt < 4; ++nt) {
                int n = n0 + warp_n * 32 + nt * 8 + tg * 2;
                float2 o;
                o.x = (acc[mt][nt][half * 2 + 0] + bias[n + 0]) * scale;
                o.y = (acc[mt][nt][half * 2 + 1] + bias[n + 1]) * scale;
                if (HEADS_OUT) {
                    int h = n >> 6;
                    int d = n & 63;
                    *(float2*)(Y + (((size_t)bidx * NH + h) * SS + t) * DD + d) = o;
                } else {
                    *(float2*)(Y + (size_t)m * HH + n) = o;
                }
            }
        }
    }
}

// ---------------------------------------------------------------------------
// Flash-style attention: one block per (b, h, 64-query tile). (unchanged)
// ---------------------------------------------------------------------------
__global__ __launch_bounds__(256) void attn_kernel(const float* __restrict__ mask,
                                                   float* __restrict__ Aout)
{
    __shared__ float Qs[64][64];  // [d][qrow]
    __shared__ float KP[64][64];  // phase 1: K^T [d][kcol]; phase 2: P [qrow][kcol]
    __shared__ float Vs[64][64];  // [kcol][d]

    const int q0 = blockIdx.x * 64;
    const int h = blockIdx.y;
    const int b = blockIdx.z;
    const int tid = threadIdx.x;
    const int ty = tid >> 4;
    const int tx = tid & 15;
    const size_t base = ((size_t)b * NH + h) * SS * DD;

#pragma unroll
    for (int p = 0; p < 4; ++p) {
        int f = tid + p * 256;
        int r = f >> 4;
        int d4 = (f & 15) << 2;
        float4 v = *(const float4*)(g_Q + base + (size_t)(q0 + r) * DD + d4);
        Qs[d4 + 0][r] = v.x;
        Qs[d4 + 1][r] = v.y;
        Qs[d4 + 2][r] = v.z;
        Qs[d4 + 3][r] = v.w;
    }

    float o[4][4];
    float mrow[4], lrow[4];
#pragma unroll
    for (int i = 0; i < 4; ++i) {
        mrow[i] = -1e30f;
        lrow[i] = 0.f;
#pragma unroll
        for (int j = 0; j < 4; ++j) o[i][j] = 0.f;
    }

    for (int k0 = 0; k0 < SS; k0 += 64) {
        __syncthreads();
#pragma unroll
        for (int p = 0; p < 4; ++p) {
            int f = tid + p * 256;
            int r = f >> 4;
            int d4 = (f & 15) << 2;
            float4 kv = *(const float4*)(g_K + base + (size_t)(k0 + r) * DD + d4);
            KP[d4 + 0][r] = kv.x;
            KP[d4 + 1][r] = kv.y;
            KP[d4 + 2][r] = kv.z;
            KP[d4 + 3][r] = kv.w;
            *(float4*)&Vs[r][d4] =
                *(const float4*)(g_V + base + (size_t)(k0 + r) * DD + d4);
        }
        __syncthreads();

        float s[4][4];
#pragma unroll
        for (int i = 0; i < 4; ++i)
#pragma unroll
            for (int j = 0; j < 4; ++j) s[i][j] = 0.f;
#pragma unroll 16
        for (int d = 0; d < 64; ++d) {
            float a[4], bb[4];
            *(float4*)&a[0]  = *(const float4*)&Qs[d][ty * 4];
            *(float4*)&bb[0] = *(const float4*)&KP[d][tx * 4];
#pragma unroll
            for (int i = 0; i < 4; ++i)
#pragma unroll
                for (int j = 0; j < 4; ++j)
                    s[i][j] = fmaf(a[i], bb[j], s[i][j]);
        }

#pragma unroll
        for (int j = 0; j < 4; ++j) {
            float mk = mask[(size_t)b * SS + k0 + tx * 4 + j] * (-1e9f);
#pragma unroll
            for (int i = 0; i < 4; ++i) s[i][j] += mk;
        }

        float pr[4][4];
#pragma unroll
        for (int i = 0; i < 4; ++i) {
            float tm = fmaxf(fmaxf(s[i][0], s[i][1]), fmaxf(s[i][2], s[i][3]));
#pragma unroll
            for (int off = 8; off; off >>= 1)
                tm = fmaxf(tm, __shfl_xor_sync(0xffffffffu, tm, off));
            float nm = fmaxf(mrow[i], tm);
            float ts = 0.f;
#pragma unroll
            for (int j = 0; j < 4; ++j) {
                pr[i][j] = __expf(s[i][j] - nm);
                ts += pr[i][j];
            }
#pragma unroll
            for (int off = 8; off; off >>= 1)
                ts += __shfl_xor_sync(0xffffffffu, ts, off);
            float corr = __expf(mrow[i] - nm);
            lrow[i] = lrow[i] * corr + ts;
            mrow[i] = nm;
#pragma unroll
            for (int j = 0; j < 4; ++j) o[i][j] *= corr;
        }

        __syncthreads();
#pragma unroll
        for (int i = 0; i < 4; ++i)
            *(float4*)&KP[ty * 4 + i][tx * 4] =
                make_float4(pr[i][0], pr[i][1], pr[i][2], pr[i][3]);
        __syncthreads();

#pragma unroll 16
        for (int kk = 0; kk < 64; ++kk) {
            float4 bv = *(const float4*)&Vs[kk][tx * 4];
            float a0 = KP[ty * 4 + 0][kk];
            float a1 = KP[ty * 4 + 1][kk];
            float a2 = KP[ty * 4 + 2][kk];
            float a3 = KP[ty * 4 + 3][kk];
            o[0][0] = fmaf(a0, bv.x, o[0][0]); o[0][1] = fmaf(a0, bv.y, o[0][1]);
            o[0][2] = fmaf(a0, bv.z, o[0][2]); o[0][3] = fmaf(a0, bv.w, o[0][3]);
            o[1][0] = fmaf(a1, bv.x, o[1][0]); o[1][1] = fmaf(a1, bv.y, o[1][1]);
            o[1][2] = fmaf(a1, bv.z, o[1][2]); o[1][3] = fmaf(a1, bv.w, o[1][3]);
            o[2][0] = fmaf(a2, bv.x, o[2][0]); o[2][1] = fmaf(a2, bv.y, o[2][1]);
            o[2][2] = fmaf(a2, bv.z, o[2][2]); o[2][3] = fmaf(a2, bv.w, o[2][3]);
            o[3][0] = fmaf(a3, bv.x, o[3][0]); o[3][1] = fmaf(a3, bv.y, o[3][1]);
            o[3][2] = fmaf(a3, bv.z, o[3][2]); o[3][3] = fmaf(a3, bv.w, o[3][3]);
        }
    }

#pragma unroll
    for (int i = 0; i < 4; ++i) {
        int q = q0 + ty * 4 + i;
        float inv = 1.f / lrow[i];
        float4 v = make_float4(o[i][0] * inv, o[i][1] * inv,
                               o[i][2] * inv, o[i][3] * inv);
        *(float4*)(Aout + ((size_t)b * SS + q) * HH + h * DD + tx * 4) = v;
    }
}

// ---------------------------------------------------------------------------
extern "C" void kernel_launch(void* const* d_in, const int* in_sizes, int n_in,
                              void* d_out, int out_size)
{
    const float* qin  = (const float*)d_in[0];
    const float* src  = (const float*)d_in[1];
    const float* mask = (const float*)d_in[2];
    const float* Wq   = (const float*)d_in[3];
    const float* bq   = (const float*)d_in[4];
    const float* Wk   = (const float*)d_in[5];
    const float* bk   = (const float*)d_in[6];
    const float* Wv   = (const float*)d_in[7];
    const float* bv   = (const float*)d_in[8];
    const float* Wo   = (const float*)d_in[9];
    const float* bo   = (const float*)d_in[10];
    float* out = (float*)d_out;

    float *gQ, *gK, *gV, *gA;
    cudaGetSymbolAddress((void**)&gQ, g_Q);
    cudaGetSymbolAddress((void**)&gK, g_K);
    cudaGetSymbolAddress((void**)&gV, g_V);
    cudaGetSymbolAddress((void**)&gA, g_A);

    dim3 gridProj(HH / 128, (BB * SS) / 128);  // (8, 32)
    gemm_conv_tc<3, true><<<gridProj, 256>>>(qin, Wq, bq, gQ, 0.125f);  // D^-0.5
    gemm_conv_tc<3, true><<<gridProj, 256>>>(src, Wk, bk, gK, 1.0f);
    gemm_conv_tc<3, true><<<gridProj, 256>>>(src, Wv, bv, gV, 1.0f);

    dim3 gridAttn(SS / 64, NH, BB);  // (32, 16, 2)
    attn_kernel<<<gridAttn, 256>>>(mask, gA);

    gemm_conv_tc<1, false><<<gridProj, 256>>>(gA, Wo, bo, out, 1.0f);
}

// round 3
// speedup vs baseline: 2.6691x; 1.6423x over previous
#include <cuda_runtime.h>
#include <math.h>
#include <stdint.h>

// Problem constants
#define BB 2
#define SS 2048
#define HH 1024
#define NH 16
#define DD 64

// Scratch: split-head Q/K/V [B, NH, S, D] and pre-Wo attention output [B*S, H]
__device__ float g_Q[(size_t)BB * NH * SS * DD];
__device__ float g_K[(size_t)BB * NH * SS * DD];
__device__ float g_V[(size_t)BB * NH * SS * DD];
__device__ float g_A[(size_t)BB * SS * HH];

// ---------------------------------------------------------------------------
// tf32 helpers
// ---------------------------------------------------------------------------
__device__ __forceinline__ uint32_t f2tf32(float x) {
    uint32_t r;
    asm("cvt.rna.tf32.f32 %0, %1;" : "=r"(r) : "f"(x));
    return r;
}

__device__ __forceinline__ void mma_tf32(float* d, const uint32_t* a, const uint32_t* b) {
    asm volatile(
        "mma.sync.aligned.m16n8k8.row.col.f32.tf32.tf32.f32 "
        "{%0,%1,%2,%3}, {%4,%5,%6,%7}, {%8,%9}, {%0,%1,%2,%3};"
        : "+f"(d[0]), "+f"(d[1]), "+f"(d[2]), "+f"(d[3])
        : "r"(a[0]), "r"(a[1]), "r"(a[2]), "r"(a[3]), "r"(b[0]), "r"(b[1]));
}

// ---------------------------------------------------------------------------
// Fused conv1d('SAME', TAPS) + bias + scale as a tf32 tensor-core GEMM.
// (unchanged from round 2)
// ---------------------------------------------------------------------------
template <int TAPS, bool HEADS_OUT>
__global__ __launch_bounds__(256) void gemm_conv_tc(
    const float* __restrict__ X, const float* __restrict__ W,
    const float* __restrict__ bias, float* __restrict__ Y, float scale)
{
    __shared__ uint32_t As[16][136];   // [k][m], tf32 bits
    __shared__ uint32_t Bs[16][136];   // [k][n], tf32 bits

    const int n0 = blockIdx.x * 128;
    const int m0 = blockIdx.y * 128;
    const int tid = threadIdx.x;
    const int wid = tid >> 5;
    const int lane = tid & 31;
    const int g = lane >> 2;
    const int tg = lane & 3;
    const int warp_m = wid >> 2;
    const int warp_n = wid & 3;

    float acc[4][4][4];
#pragma unroll
    for (int i = 0; i < 4; ++i)
#pragma unroll
        for (int j = 0; j < 4; ++j)
#pragma unroll
            for (int r = 0; r < 4; ++r) acc[i][j][r] = 0.f;

    const int CENTER = (TAPS - 1) / 2;

    for (int tap = 0; tap < TAPS; ++tap) {
        const float* Wt = W + (size_t)tap * HH * HH;
        for (int c0 = 0; c0 < HH; c0 += 16) {
#pragma unroll
            for (int p = 0; p < 2; ++p) {
                int f = tid + p * 256;
                int row = f >> 2;
                int c4 = (f & 3) << 2;
                int m = m0 + row;
                int bidx = m >> 11;
                int t = m & (SS - 1);
                int srow = t + tap - CENTER;
                float4 v = make_float4(0.f, 0.f, 0.f, 0.f);
                if (srow >= 0 && srow < SS)
                    v = *(const float4*)(X + ((size_t)bidx * SS + srow) * HH + c0 + c4);
                As[c4 + 0][row] = f2tf32(v.x);
                As[c4 + 1][row] = f2tf32(v.y);
                As[c4 + 2][row] = f2tf32(v.z);
                As[c4 + 3][row] = f2tf32(v.w);
            }
#pragma unroll
            for (int p = 0; p < 2; ++p) {
                int f = tid + p * 256;
                int kk = f >> 5;
                int c4 = (f & 31) << 2;
                float4 v = *(const float4*)(Wt + (size_t)(c0 + kk) * HH + n0 + c4);
                uint4 u;
                u.x = f2tf32(v.x); u.y = f2tf32(v.y);
                u.z = f2tf32(v.z); u.w = f2tf32(v.w);
                *(uint4*)&Bs[kk][c4] = u;
            }
            __syncthreads();

#pragma unroll
            for (int ks = 0; ks < 2; ++ks) {
                const int kb = ks * 8;
                uint32_t a[4][4];
                uint32_t b[4][2];
#pragma unroll
                for (int mt = 0; mt < 4; ++mt) {
                    int mr = warp_m * 64 + mt * 16 + g;
                    a[mt][0] = As[kb + tg][mr];
                    a[mt][1] = As[kb + tg][mr + 8];
                    a[mt][2] = As[kb + tg + 4][mr];
                    a[mt][3] = As[kb + tg + 4][mr + 8];
                }
#pragma unroll
                for (int nt = 0; nt < 4; ++nt) {
                    int nc = warp_n * 32 + nt * 8 + g;
                    b[nt][0] = Bs[kb + tg][nc];
                    b[nt][1] = Bs[kb + tg + 4][nc];
                }
#pragma unroll
                for (int mt = 0; mt < 4; ++mt)
#pragma unroll
                    for (int nt = 0; nt < 4; ++nt)
                        mma_tf32(acc[mt][nt], a[mt], b[nt]);
            }
            __syncthreads();
        }
    }

#pragma unroll
    for (int mt = 0; mt < 4; ++mt) {
#pragma unroll
        for (int half = 0; half < 2; ++half) {
            int m = m0 + warp_m * 64 + mt * 16 + g + half * 8;
            int bidx = m >> 11;
            int t = m & (SS - 1);
#pragma unroll
            for (int nt = 0; nt < 4; ++nt) {
                int n = n0 + warp_n * 32 + nt * 8 + tg * 2;
                float2 o;
                o.x = (acc[mt][nt][half * 2 + 0] + bias[n + 0]) * scale;
                o.y = (acc[mt][nt][half * 2 + 1] + bias[n + 1]) * scale;
                if (HEADS_OUT) {
                    int h = n >> 6;
                    int d = n & 63;
                    *(float2*)(Y + (((size_t)bidx * NH + h) * SS + t) * DD + d) = o;
                } else {
                    *(float2*)(Y + (size_t)m * HH + n) = o;
                }
            }
        }
    }
}

// ---------------------------------------------------------------------------
// Tensor-core flash attention (tf32 m16n8k8).
// Block = (b, h, 128-query tile), 256 threads = 8 warps x 16 query rows.
// Q fragments held in registers for the whole kernel. K/V staged per 64-key
// tile in smem with conflict-free strides (76 / 72 words).
// Online softmax on accumulator fragments; P transposed to A-operand layout
// via in-register shfl (no smem round trip).
// ---------------------------------------------------------------------------
__global__ __launch_bounds__(256) void attn_tc(const float* __restrict__ mask,
                                               float* __restrict__ Aout)
{
    __shared__ uint32_t Kn[64][76];  // K tile, natural [key][d], tf32 bits
    __shared__ uint32_t Vs[64][72];  // V tile, natural [key][d], tf32 bits
    __shared__ float msk[SS];        // mask row * -1e9

    const int q0 = blockIdx.x * 128;
    const int h = blockIdx.y;
    const int b = blockIdx.z;
    const int tid = threadIdx.x;
    const int wid = tid >> 5;
    const int lane = tid & 31;
    const int g = lane >> 2;       // 0..7
    const int tg = lane & 3;       // 0..3
    const size_t base = ((size_t)b * NH + h) * SS * DD;
    const int qr = q0 + wid * 16;  // warp's first query row

    // mask row -> smem (premultiplied)
    for (int i = tid; i < SS; i += 256)
        msk[i] = mask[(size_t)b * SS + i] * (-1e9f);

    // Q A-fragments in registers: rows qr+g / qr+g+8, k = 8*ks + {tg, tg+4}
    uint32_t qa[8][4];
    {
        const float* Qp = g_Q + base + (size_t)(qr + g) * DD + tg;
#pragma unroll
        for (int ks = 0; ks < 8; ++ks) {
            qa[ks][0] = f2tf32(Qp[ks * 8]);
            qa[ks][1] = f2tf32(Qp[ks * 8 + 8 * DD]);
            qa[ks][2] = f2tf32(Qp[ks * 8 + 4]);
            qa[ks][3] = f2tf32(Qp[ks * 8 + 4 + 8 * DD]);
        }
    }

    float oacc[8][4];
#pragma unroll
    for (int nt = 0; nt < 8; ++nt)
#pragma unroll
        for (int r = 0; r < 4; ++r) oacc[nt][r] = 0.f;
    float m0 = -1e30f, m8 = -1e30f, l0 = 0.f, l8 = 0.f;

    for (int k0 = 0; k0 < SS; k0 += 64) {
        __syncthreads();  // prev tile consumed / msk ready
        // Stage K,V tiles (each thread: 4 float4 loads per tensor)
#pragma unroll
        for (int p = 0; p < 4; ++p) {
            int f = tid + p * 256;       // 0..1023
            int r = f >> 4;              // key row 0..63
            int c4 = (f & 15) << 2;      // d: 0,4,...,60
            float4 kv = *(const float4*)(g_K + base + (size_t)(k0 + r) * DD + c4);
            float4 vv = *(const float4*)(g_V + base + (size_t)(k0 + r) * DD + c4);
            uint4 uk, uv;
            uk.x = f2tf32(kv.x); uk.y = f2tf32(kv.y);
            uk.z = f2tf32(kv.z); uk.w = f2tf32(kv.w);
            uv.x = f2tf32(vv.x); uv.y = f2tf32(vv.y);
            uv.z = f2tf32(vv.z); uv.w = f2tf32(vv.w);
            *(uint4*)&Kn[r][c4] = uk;
            *(uint4*)&Vs[r][c4] = uv;
        }
        __syncthreads();

        // S = Q K^T : S[16q x 64key] per warp, 8 n-frags
        float sacc[8][4];
#pragma unroll
        for (int nt = 0; nt < 8; ++nt)
#pragma unroll
            for (int r = 0; r < 4; ++r) sacc[nt][r] = 0.f;
#pragma unroll
        for (int ks = 0; ks < 8; ++ks) {
#pragma unroll
            for (int nt = 0; nt < 8; ++nt) {
                uint32_t bfr[2];
                bfr[0] = Kn[nt * 8 + g][ks * 8 + tg];       // B[k=d][n=key]
                bfr[1] = Kn[nt * 8 + g][ks * 8 + tg + 4];
                mma_tf32(sacc[nt], qa[ks], bfr);
            }
        }

        // additive mask
#pragma unroll
        for (int nt = 0; nt < 8; ++nt) {
            float mk0 = msk[k0 + nt * 8 + 2 * tg];
            float mk1 = msk[k0 + nt * 8 + 2 * tg + 1];
            sacc[nt][0] += mk0; sacc[nt][1] += mk1;
            sacc[nt][2] += mk0; sacc[nt][3] += mk1;
        }

        // row maxes (rows g and g+8)
        float r0 = -1e30f, r8 = -1e30f;
#pragma unroll
        for (int nt = 0; nt < 8; ++nt) {
            r0 = fmaxf(r0, fmaxf(sacc[nt][0], sacc[nt][1]));
            r8 = fmaxf(r8, fmaxf(sacc[nt][2], sacc[nt][3]));
        }
        r0 = fmaxf(r0, __shfl_xor_sync(0xffffffffu, r0, 1));
        r0 = fmaxf(r0, __shfl_xor_sync(0xffffffffu, r0, 2));
        r8 = fmaxf(r8, __shfl_xor_sync(0xffffffffu, r8, 1));
        r8 = fmaxf(r8, __shfl_xor_sync(0xffffffffu, r8, 2));

        float nm0 = fmaxf(m0, r0), nm8 = fmaxf(m8, r8);
        float cr0 = __expf(m0 - nm0), cr8 = __expf(m8 - nm8);

        // P = exp(S - m), row sums
        float s0 = 0.f, s8 = 0.f;
#pragma unroll
        for (int nt = 0; nt < 8; ++nt) {
            sacc[nt][0] = __expf(sacc[nt][0] - nm0);
            sacc[nt][1] = __expf(sacc[nt][1] - nm0);
            sacc[nt][2] = __expf(sacc[nt][2] - nm8);
            sacc[nt][3] = __expf(sacc[nt][3] - nm8);
            s0 += sacc[nt][0] + sacc[nt][1];
            s8 += sacc[nt][2] + sacc[nt][3];
        }
        s0 += __shfl_xor_sync(0xffffffffu, s0, 1);
        s0 += __shfl_xor_sync(0xffffffffu, s0, 2);
        s8 += __shfl_xor_sync(0xffffffffu, s8, 1);
        s8 += __shfl_xor_sync(0xffffffffu, s8, 2);

        l0 = l0 * cr0 + s0;
        l8 = l8 * cr8 + s8;
        m0 = nm0; m8 = nm8;

#pragma unroll
        for (int nt = 0; nt < 8; ++nt) {
            oacc[nt][0] *= cr0; oacc[nt][1] *= cr0;
            oacc[nt][2] *= cr8; oacc[nt][3] *= cr8;
        }

        // O += P V : transpose each P frag (C layout) to A layout via shfl
        const int src0 = (g << 2) + (tg >> 1);
        const int src2 = src0 + 2;
        const bool odd = tg & 1;
#pragma unroll
        for (int ks = 0; ks < 8; ++ks) {
            float e00 = __shfl_sync(0xffffffffu, sacc[ks][0], src0);
            float e01 = __shfl_sync(0xffffffffu, sacc[ks][1], src0);
            float e10 = __shfl_sync(0xffffffffu, sacc[ks][2], src0);
            float e11 = __shfl_sync(0xffffffffu, sacc[ks][3], src0);
            float e20 = __shfl_sync(0xffffffffu, sacc[ks][0], src2);
            float e21 = __shfl_sync(0xffffffffu, sacc[ks][1], src2);
            float e30 = __shfl_sync(0xffffffffu, sacc[ks][2], src2);
            float e31 = __shfl_sync(0xffffffffu, sacc[ks][3], src2);
            uint32_t pa[4];
            pa[0] = f2tf32(odd ? e01 : e00);  // row g,   k=tg
            pa[1] = f2tf32(odd ? e11 : e10);  // row g+8, k=tg
            pa[2] = f2tf32(odd ? e21 : e20);  // row g,   k=tg+4
            pa[3] = f2tf32(odd ? e31 : e30);  // row g+8, k=tg+4
#pragma unroll
            for (int nt = 0; nt < 8; ++nt) {
                uint32_t bfr[2];
                bfr[0] = Vs[ks * 8 + tg][nt * 8 + g];       // B[k=key][n=d]
                bfr[1] = Vs[ks * 8 + tg + 4][nt * 8 + g];
                mma_tf32(oacc[nt], pa, bfr);
            }
        }
    }

    // Epilogue: normalize, write merged-head [B, S, H]
    const float inv0 = 1.f / l0, inv8 = 1.f / l8;
#pragma unroll
    for (int nt = 0; nt < 8; ++nt) {
        float2 o0, o8;
        o0.x = oacc[nt][0] * inv0; o0.y = oacc[nt][1] * inv0;
        o8.x = oacc[nt][2] * inv8; o8.y = oacc[nt][3] * inv8;
        size_t col = (size_t)h * DD + nt * 8 + 2 * tg;
        *(float2*)(Aout + ((size_t)b * SS + qr + g) * HH + col) = o0;
        *(float2*)(Aout + ((size_t)b * SS + qr + g + 8) * HH + col) = o8;
    }
}

// ---------------------------------------------------------------------------
extern "C" void kernel_launch(void* const* d_in, const int* in_sizes, int n_in,
                              void* d_out, int out_size)
{
    const float* qin  = (const float*)d_in[0];
    const float* src  = (const float*)d_in[1];
    const float* mask = (const float*)d_in[2];
    const float* Wq   = (const float*)d_in[3];
    const float* bq   = (const float*)d_in[4];
    const float* Wk   = (const float*)d_in[5];
    const float* bk   = (const float*)d_in[6];
    const float* Wv   = (const float*)d_in[7];
    const float* bv   = (const float*)d_in[8];
    const float* Wo   = (const float*)d_in[9];
    const float* bo   = (const float*)d_in[10];
    float* out = (float*)d_out;

    float *gQ, *gK, *gV, *gA;
    cudaGetSymbolAddress((void**)&gQ, g_Q);
    cudaGetSymbolAddress((void**)&gK, g_K);
    cudaGetSymbolAddress((void**)&gV, g_V);
    cudaGetSymbolAddress((void**)&gA, g_A);

    dim3 gridProj(HH / 128, (BB * SS) / 128);  // (8, 32)
    gemm_conv_tc<3, true><<<gridProj, 256>>>(qin, Wq, bq, gQ, 0.125f);  // D^-0.5
    gemm_conv_tc<3, true><<<gridProj, 256>>>(src, Wk, bk, gK, 1.0f);
    gemm_conv_tc<3, true><<<gridProj, 256>>>(src, Wv, bv, gV, 1.0f);

    dim3 gridAttn(SS / 128, NH, BB);  // (16, 16, 2)
    attn_tc<<<gridAttn, 256>>>(mask, gA);

    gemm_conv_tc<1, false><<<gridProj, 256>>>(gA, Wo, bo, out, 1.0f);
}

// round 4
// speedup vs baseline: 2.8086x; 1.0523x over previous
#include <cuda_runtime.h>
#include <math.h>
#include <stdint.h>

// Problem constants
#define BB 2
#define SS 2048
#define HH 1024
#define NH 16
#define DD 64

// Scratch: split-head Q/K/V [B, NH, S, D] and pre-Wo attention output [B*S, H]
__device__ float g_Q[(size_t)BB * NH * SS * DD];
__device__ float g_K[(size_t)BB * NH * SS * DD];
__device__ float g_V[(size_t)BB * NH * SS * DD];
__device__ float g_A[(size_t)BB * SS * HH];

// ---------------------------------------------------------------------------
// tf32 helpers
// ---------------------------------------------------------------------------
__device__ __forceinline__ uint32_t f2tf32(float x) {
    uint32_t r;
    asm("cvt.rna.tf32.f32 %0, %1;" : "=r"(r) : "f"(x));
    return r;
}

__device__ __forceinline__ void mma_tf32(float* d, const uint32_t* a, const uint32_t* b) {
    asm volatile(
        "mma.sync.aligned.m16n8k8.row.col.f32.tf32.tf32.f32 "
        "{%0,%1,%2,%3}, {%4,%5,%6,%7}, {%8,%9}, {%0,%1,%2,%3};"
        : "+f"(d[0]), "+f"(d[1]), "+f"(d[2]), "+f"(d[3])
        : "r"(a[0]), "r"(a[1]), "r"(a[2]), "r"(a[3]), "r"(b[0]), "r"(b[1]));
}

// ---------------------------------------------------------------------------
// Fused conv1d('SAME', TAPS) + bias + scale as a tf32 tensor-core GEMM core.
// BM=128, BN=128, BK=16. 256 threads = 8 warps (2m x 4n), warp tile 64x32.
// Double-buffered smem, register-staged global loads, 1 sync / k-iteration.
// A smem uses XOR swizzle col = row ^ (((k>>2)&3)<<3): conflict-free STS
// AND conflict-free fragment LDS (stride 136 => bank = 8k + col mod 32).
// Accumulation order identical to round-3 kernel (bit-identical results).
// ---------------------------------------------------------------------------
template <int TAPS, bool HEADS_OUT>
__device__ __forceinline__ void conv_gemm_core(
    const float* __restrict__ X, const float* __restrict__ W,
    const float* __restrict__ bias, float* __restrict__ Y, float scale,
    int m0, int n0)
{
    __shared__ uint32_t As[2][16][136];   // [buf][k][m^sigma], tf32 bits
    __shared__ uint32_t Bs[2][16][136];   // [buf][k][n], tf32 bits

    const int tid = threadIdx.x;
    const int wid = tid >> 5;
    const int lane = tid & 31;
    const int g = lane >> 2;
    const int tg = lane & 3;
    const int warp_m = wid >> 2;
    const int warp_n = wid & 3;

    // Fixed per-thread staging coordinates
    int arow[2], ac4[2], at[2], ab[2], asw[2];
    int bkk[2], bc4[2];
#pragma unroll
    for (int p = 0; p < 2; ++p) {
        int f = tid + p * 256;
        arow[p] = f >> 2;
        ac4[p] = (f & 3) << 2;
        asw[p] = arow[p] ^ (((ac4[p] >> 2) & 3) << 3);   // swizzled column
        int m = m0 + arow[p];
        ab[p] = m >> 11;
        at[p] = m & (SS - 1);
        bkk[p] = f >> 5;
        bc4[p] = (f & 31) << 2;
    }

    float acc[4][4][4];
#pragma unroll
    for (int i = 0; i < 4; ++i)
#pragma unroll
        for (int j = 0; j < 4; ++j)
#pragma unroll
            for (int r = 0; r < 4; ++r) acc[i][j][r] = 0.f;

    const int CENTER = (TAPS - 1) / 2;
    const int NIT = TAPS * 64;

    float4 va[2], vb[2];

    auto issue_loads = [&](int it) {
        int tap = it >> 6;            // HH/16 == 64
        int c0 = (it & 63) << 4;
        const float* Wt = W + (size_t)tap * HH * HH;
#pragma unroll
        for (int p = 0; p < 2; ++p) {
            int srow = at[p] + tap - CENTER;
            va[p] = make_float4(0.f, 0.f, 0.f, 0.f);
            if (srow >= 0 && srow < SS)
                va[p] = *(const float4*)(X + ((size_t)ab[p] * SS + srow) * HH + c0 + ac4[p]);
            vb[p] = *(const float4*)(Wt + (size_t)(c0 + bkk[p]) * HH + n0 + bc4[p]);
        }
    };
    auto store_tiles = [&](int buf) {
#pragma unroll
        for (int p = 0; p < 2; ++p) {
            As[buf][ac4[p] + 0][asw[p]] = f2tf32(va[p].x);
            As[buf][ac4[p] + 1][asw[p]] = f2tf32(va[p].y);
            As[buf][ac4[p] + 2][asw[p]] = f2tf32(va[p].z);
            As[buf][ac4[p] + 3][asw[p]] = f2tf32(va[p].w);
            uint4 u;
            u.x = f2tf32(vb[p].x); u.y = f2tf32(vb[p].y);
            u.z = f2tf32(vb[p].z); u.w = f2tf32(vb[p].w);
            *(uint4*)&Bs[buf][bkk[p]][bc4[p]] = u;
        }
    };

    // Prologue
    issue_loads(0);
    store_tiles(0);
    __syncthreads();

    for (int it = 0; it < NIT; ++it) {
        const int buf = it & 1;
        if (it + 1 < NIT) issue_loads(it + 1);

#pragma unroll
        for (int ks = 0; ks < 2; ++ks) {
            const int kb = ks * 8;
            const int k1 = kb + tg;
            const int k2 = kb + tg + 4;
            const int s1 = ((k1 >> 2) & 3) << 3;
            const int s2 = ((k2 >> 2) & 3) << 3;
            uint32_t a[4][4];
            uint32_t b[4][2];
#pragma unroll
            for (int mt = 0; mt < 4; ++mt) {
                int mr = warp_m * 64 + mt * 16 + g;
                a[mt][0] = As[buf][k1][mr ^ s1];
                a[mt][1] = As[buf][k1][(mr + 8) ^ s1];
                a[mt][2] = As[buf][k2][mr ^ s2];
                a[mt][3] = As[buf][k2][(mr + 8) ^ s2];
            }
#pragma unroll
            for (int nt = 0; nt < 4; ++nt) {
                int nc = warp_n * 32 + nt * 8 + g;
                b[nt][0] = Bs[buf][k1][nc];
                b[nt][1] = Bs[buf][k2][nc];
            }
#pragma unroll
            for (int mt = 0; mt < 4; ++mt)
#pragma unroll
                for (int nt = 0; nt < 4; ++nt)
                    mma_tf32(acc[mt][nt], a[mt], b[nt]);
        }

        if (it + 1 < NIT) {
            store_tiles(buf ^ 1);
            __syncthreads();
        }
    }

    // Epilogue: bias, scale, layout
#pragma unroll
    for (int mt = 0; mt < 4; ++mt) {
#pragma unroll
        for (int half = 0; half < 2; ++half) {
            int m = m0 + warp_m * 64 + mt * 16 + g + half * 8;
            int bidx = m >> 11;
            int t = m & (SS - 1);
#pragma unroll
            for (int nt = 0; nt < 4; ++nt) {
                int n = n0 + warp_n * 32 + nt * 8 + tg * 2;
                float2 o;
                o.x = (acc[mt][nt][half * 2 + 0] + bias[n + 0]) * scale;
                o.y = (acc[mt][nt][half * 2 + 1] + bias[n + 1]) * scale;
                if (HEADS_OUT) {
                    int h = n >> 6;
                    int d = n & 63;
                    *(float2*)(Y + (((size_t)bidx * NH + h) * SS + t) * DD + d) = o;
                } else {
                    *(float2*)(Y + (size_t)m * HH + n) = o;
                }
            }
        }
    }
}

// Merged Q/K/V conv launch: grid.z selects the projection.
struct Conv3Args {
    const float* X0;            // query_input (z==0)
    const float* X1;            // source_input (z==1,2)
    const float* W[3];
    const float* b[3];
    float* Y[3];
    float scale[3];
};

__global__ __launch_bounds__(256, 2) void conv3_kernel(Conv3Args a)
{
    const int z = blockIdx.z;
    const float* X = (z == 0) ? a.X0 : a.X1;
    conv_gemm_core<3, true>(X, a.W[z], a.b[z], a.Y[z], a.scale[z],
                            blockIdx.y * 128, blockIdx.x * 128);
}

__global__ __launch_bounds__(256, 2) void outproj_kernel(
    const float* __restrict__ X, const float* __restrict__ W,
    const float* __restrict__ bias, float* __restrict__ Y)
{
    conv_gemm_core<1, false>(X, W, bias, Y, 1.0f,
                             blockIdx.y * 128, blockIdx.x * 128);
}

// ---------------------------------------------------------------------------
// Tensor-core flash attention (tf32 m16n8k8) — unchanged from round 3.
// ---------------------------------------------------------------------------
__global__ __launch_bounds__(256) void attn_tc(const float* __restrict__ mask,
                                               float* __restrict__ Aout)
{
    __shared__ uint32_t Kn[64][76];  // K tile, natural [key][d], tf32 bits
    __shared__ uint32_t Vs[64][72];  // V tile, natural [key][d], tf32 bits
    __shared__ float msk[SS];        // mask row * -1e9

    const int q0 = blockIdx.x * 128;
    const int h = blockIdx.y;
    const int b = blockIdx.z;
    const int tid = threadIdx.x;
    const int wid = tid >> 5;
    const int lane = tid & 31;
    const int g = lane >> 2;
    const int tg = lane & 3;
    const size_t base = ((size_t)b * NH + h) * SS * DD;
    const int qr = q0 + wid * 16;

    for (int i = tid; i < SS; i += 256)
        msk[i] = mask[(size_t)b * SS + i] * (-1e9f);

    uint32_t qa[8][4];
    {
        const float* Qp = g_Q + base + (size_t)(qr + g) * DD + tg;
#pragma unroll
        for (int ks = 0; ks < 8; ++ks) {
            qa[ks][0] = f2tf32(Qp[ks * 8]);
            qa[ks][1] = f2tf32(Qp[ks * 8 + 8 * DD]);
            qa[ks][2] = f2tf32(Qp[ks * 8 + 4]);
            qa[ks][3] = f2tf32(Qp[ks * 8 + 4 + 8 * DD]);
        }
    }

    float oacc[8][4];
#pragma unroll
    for (int nt = 0; nt < 8; ++nt)
#pragma unroll
        for (int r = 0; r < 4; ++r) oacc[nt][r] = 0.f;
    float m0 = -1e30f, m8 = -1e30f, l0 = 0.f, l8 = 0.f;

    for (int k0 = 0; k0 < SS; k0 += 64) {
        __syncthreads();
#pragma unroll
        for (int p = 0; p < 4; ++p) {
            int f = tid + p * 256;
            int r = f >> 4;
            int c4 = (f & 15) << 2;
            float4 kv = *(const float4*)(g_K + base + (size_t)(k0 + r) * DD + c4);
            float4 vv = *(const float4*)(g_V + base + (size_t)(k0 + r) * DD + c4);
            uint4 uk, uv;
            uk.x = f2tf32(kv.x); uk.y = f2tf32(kv.y);
            uk.z = f2tf32(kv.z); uk.w = f2tf32(kv.w);
            uv.x = f2tf32(vv.x); uv.y = f2tf32(vv.y);
            uv.z = f2tf32(vv.z); uv.w = f2tf32(vv.w);
            *(uint4*)&Kn[r][c4] = uk;
            *(uint4*)&Vs[r][c4] = uv;
        }
        __syncthreads();

        float sacc[8][4];
#pragma unroll
        for (int nt = 0; nt < 8; ++nt)
#pragma unroll
            for (int r = 0; r < 4; ++r) sacc[nt][r] = 0.f;
#pragma unroll
        for (int ks = 0; ks < 8; ++ks) {
#pragma unroll
            for (int nt = 0; nt < 8; ++nt) {
                uint32_t bfr[2];
                bfr[0] = Kn[nt * 8 + g][ks * 8 + tg];
                bfr[1] = Kn[nt * 8 + g][ks * 8 + tg + 4];
                mma_tf32(sacc[nt], qa[ks], bfr);
            }
        }

#pragma unroll
        for (int nt = 0; nt < 8; ++nt) {
            float mk0 = msk[k0 + nt * 8 + 2 * tg];
            float mk1 = msk[k0 + nt * 8 + 2 * tg + 1];
            sacc[nt][0] += mk0; sacc[nt][1] += mk1;
            sacc[nt][2] += mk0; sacc[nt][3] += mk1;
        }

        float r0 = -1e30f, r8 = -1e30f;
#pragma unroll
        for (int nt = 0; nt < 8; ++nt) {
            r0 = fmaxf(r0, fmaxf(sacc[nt][0], sacc[nt][1]));
            r8 = fmaxf(r8, fmaxf(sacc[nt][2], sacc[nt][3]));
        }
        r0 = fmaxf(r0, __shfl_xor_sync(0xffffffffu, r0, 1));
        r0 = fmaxf(r0, __shfl_xor_sync(0xffffffffu, r0, 2));
        r8 = fmaxf(r8, __shfl_xor_sync(0xffffffffu, r8, 1));
        r8 = fmaxf(r8, __shfl_xor_sync(0xffffffffu, r8, 2));

        float nm0 = fmaxf(m0, r0), nm8 = fmaxf(m8, r8);
        float cr0 = __expf(m0 - nm0), cr8 = __expf(m8 - nm8);

        float s0 = 0.f, s8 = 0.f;
#pragma unroll
        for (int nt = 0; nt < 8; ++nt) {
            sacc[nt][0] = __expf(sacc[nt][0] - nm0);
            sacc[nt][1] = __expf(sacc[nt][1] - nm0);
            sacc[nt][2] = __expf(sacc[nt][2] - nm8);
            sacc[nt][3] = __expf(sacc[nt][3] - nm8);
            s0 += sacc[nt][0] + sacc[nt][1];
            s8 += sacc[nt][2] + sacc[nt][3];
        }
        s0 += __shfl_xor_sync(0xffffffffu, s0, 1);
        s0 += __shfl_xor_sync(0xffffffffu, s0, 2);
        s8 += __shfl_xor_sync(0xffffffffu, s8, 1);
        s8 += __shfl_xor_sync(0xffffffffu, s8, 2);

        l0 = l0 * cr0 + s0;
        l8 = l8 * cr8 + s8;
        m0 = nm0; m8 = nm8;

#pragma unroll
        for (int nt = 0; nt < 8; ++nt) {
            oacc[nt][0] *= cr0; oacc[nt][1] *= cr0;
            oacc[nt][2] *= cr8; oacc[nt][3] *= cr8;
        }

        const int src0 = (g << 2) + (tg >> 1);
        const int src2 = src0 + 2;
        const bool odd = tg & 1;
#pragma unroll
        for (int ks = 0; ks < 8; ++ks) {
            float e00 = __shfl_sync(0xffffffffu, sacc[ks][0], src0);
            float e01 = __shfl_sync(0xffffffffu, sacc[ks][1], src0);
            float e10 = __shfl_sync(0xffffffffu, sacc[ks][2], src0);
            float e11 = __shfl_sync(0xffffffffu, sacc[ks][3], src0);
            float e20 = __shfl_sync(0xffffffffu, sacc[ks][0], src2);
            float e21 = __shfl_sync(0xffffffffu, sacc[ks][1], src2);
            float e30 = __shfl_sync(0xffffffffu, sacc[ks][2], src2);
            float e31 = __shfl_sync(0xffffffffu, sacc[ks][3], src2);
            uint32_t pa[4];
            pa[0] = f2tf32(odd ? e01 : e00);
            pa[1] = f2tf32(odd ? e11 : e10);
            pa[2] = f2tf32(odd ? e21 : e20);
            pa[3] = f2tf32(odd ? e31 : e30);
#pragma unroll
            for (int nt = 0; nt < 8; ++nt) {
                uint32_t bfr[2];
                bfr[0] = Vs[ks * 8 + tg][nt * 8 + g];
                bfr[1] = Vs[ks * 8 + tg + 4][nt * 8 + g];
                mma_tf32(oacc[nt], pa, bfr);
            }
        }
    }

    const float inv0 = 1.f / l0, inv8 = 1.f / l8;
#pragma unroll
    for (int nt = 0; nt < 8; ++nt) {
        float2 o0, o8;
        o0.x = oacc[nt][0] * inv0; o0.y = oacc[nt][1] * inv0;
        o8.x = oacc[nt][2] * inv8; o8.y = oacc[nt][3] * inv8;
        size_t col = (size_t)h * DD + nt * 8 + 2 * tg;
        *(float2*)(Aout + ((size_t)b * SS + qr + g) * HH + col) = o0;
        *(float2*)(Aout + ((size_t)b * SS + qr + g + 8) * HH + col) = o8;
    }
}

// ---------------------------------------------------------------------------
extern "C" void kernel_launch(void* const* d_in, const int* in_sizes, int n_in,
                              void* d_out, int out_size)
{
    const float* qin  = (const float*)d_in[0];
    const float* src  = (const float*)d_in[1];
    const float* mask = (const float*)d_in[2];
    const float* Wq   = (const float*)d_in[3];
    const float* bq   = (const float*)d_in[4];
    const float* Wk   = (const float*)d_in[5];
    const float* bk   = (const float*)d_in[6];
    const float* Wv   = (const float*)d_in[7];
    const float* bv   = (const float*)d_in[8];
    const float* Wo   = (const float*)d_in[9];
    const float* bo   = (const float*)d_in[10];
    float* out = (float*)d_out;

    float *gQ, *gK, *gV, *gA;
    cudaGetSymbolAddress((void**)&gQ, g_Q);
    cudaGetSymbolAddress((void**)&gK, g_K);
    cudaGetSymbolAddress((void**)&gV, g_V);
    cudaGetSymbolAddress((void**)&gA, g_A);

    Conv3Args a;
    a.X0 = qin; a.X1 = src;
    a.W[0] = Wq; a.W[1] = Wk; a.W[2] = Wv;
    a.b[0] = bq; a.b[1] = bk; a.b[2] = bv;
    a.Y[0] = gQ; a.Y[1] = gK; a.Y[2] = gV;
    a.scale[0] = 0.125f; a.scale[1] = 1.0f; a.scale[2] = 1.0f;

    dim3 gridConv3(HH / 128, (BB * SS) / 128, 3);  // (8, 32, 3)
    conv3_kernel<<<gridConv3, 256>>>(a);

    dim3 gridAttn(SS / 128, NH, BB);  // (16, 16, 2)
    attn_tc<<<gridAttn, 256>>>(mask, gA);

    dim3 gridProj(HH / 128, (BB * SS) / 128);  // (8, 32)
    outproj_kernel<<<gridProj, 256>>>(gA, Wo, bo, out);
}